// round 12
// baseline (speedup 1.0000x reference)
#include <cuda_runtime.h>
#include <cuda_fp16.h>
#include <math.h>

#define NN 100000
#define NE 1200000
#define FIN 128
#define FHID 64
#define FOUT 40

typedef unsigned long long ull;

// ---------------- scratch (device globals) ----------------
// g_zero: [0,NN) = degree histogram, [NN, NN+128) = scan ready-flags.
// Zeroed by the PREVIOUS launch's agg_final (static init covers call #1).
__device__ int    g_zero[NN + 128];
__device__ int    g_barrier[2];             // grid-barrier counters (same re-zero scheme)
__device__ int    g_rowptr[NN + 1];
__device__ int    g_cursor[NN];
__device__ int    g_col[NE];
__device__ float  g_dis[NN];
__device__ __half g_Hh[(size_t)NN * FHID];  // fp16 message buffer (layers 1-3)
__device__ float  g_Z[(size_t)NN * FHID];   // aggregated fp32 buffer

constexpr int CSR_BLOCKS = 98;   // all co-resident on 148 SMs (1024 thr => 2 blocks/SM max)
constexpr int CSR_THREADS = 1024;

// ---------------- side stream for capture fork-join (created pre-main) ----------------
struct SideStream {
    cudaStream_t s1;
    cudaEvent_t evFork, evJoin;
    SideStream() {
        cudaStreamCreateWithFlags(&s1, cudaStreamNonBlocking);
        cudaEventCreateWithFlags(&evFork, cudaEventDisableTiming);
        cudaEventCreateWithFlags(&evJoin, cudaEventDisableTiming);
    }
};
static SideStream g_ss;

// ---------------- packed f32x2 helpers (Blackwell FFMA2) ----------------
__device__ __forceinline__ ull bcast2(float f) {
    ull r;
    asm("mov.b64 %0, {%1, %1};" : "=l"(r) : "f"(f));
    return r;
}
__device__ __forceinline__ void fma2(ull& d, ull a, ull b) {
    asm("fma.rn.f32x2 %0, %1, %2, %0;" : "+l"(d) : "l"(a), "l"(b));
}
__device__ __forceinline__ void unpack2(float& lo, float& hi, ull v) {
    asm("mov.b64 {%0, %1}, %2;" : "=f"(lo), "=f"(hi) : "l"(v));
}

// ---------------- per-block edge dtype detection ----------------
__device__ __forceinline__ int detect_is64(const int* e) {
    int t = threadIdx.x;
    int pred = 1;
    if (t < 128) pred = (e[2 * t + 1] == 0);
    return __syncthreads_and(pred);
}

__device__ __forceinline__ int edge_at(const void* e, long long idx, int is64) {
    if (is64) return (int)((const long long*)e)[idx];
    return ((const int*)e)[idx];
}

// ---------------- software grid barrier (all CSR_BLOCKS co-resident) ----------------
__device__ __forceinline__ void grid_barrier(int which) {
    __threadfence();
    __syncthreads();
    if (threadIdx.x == 0) {
        atomicAdd(&g_barrier[which], 1);
        while (atomicAdd(&g_barrier[which], 0) < CSR_BLOCKS) {}
    }
    __syncthreads();
}

// ---------------- fused CSR build: hist -> scan -> fill in ONE kernel ----------------
__global__ void __launch_bounds__(CSR_THREADS) k_csr(const void* __restrict__ e) {
    int is64 = detect_is64((const int*)e);
    int b    = blockIdx.x;
    int tid  = threadIdx.x;
    int gtid = b * CSR_THREADS + tid;
    const int NT = CSR_BLOCKS * CSR_THREADS;  // 100352

    // ---- phase A: degree histogram (RED path: result unused) ----
    for (int i = gtid; i < NE; i += NT) {
        int d = edge_at(e, (long long)NE + i, is64);
        atomicAdd(&g_zero[d], 1);
    }

    grid_barrier(0);

    // ---- phase B: scan (deg -> rowptr, cursor, dis); decoupled lookback ----
    {
        __shared__ int wsum[32];
        __shared__ int s_off;
        int lane = tid & 31;
        int wid  = tid >> 5;
        int idx  = gtid;  // one element per thread, NT >= NN
        int* ready = &g_zero[NN];

        int v = (idx < NN) ? g_zero[idx] : 0;
        if (idx < NN) g_dis[idx] = rsqrtf((float)(v + 1));
        if (tid == 0) s_off = 0;

        int x = v;
#pragma unroll
        for (int off = 1; off < 32; off <<= 1) {
            int y = __shfl_up_sync(0xFFFFFFFFu, x, off);
            if (lane >= off) x += y;
        }
        if (lane == 31) wsum[wid] = x;
        __syncthreads();
        if (wid == 0) {
            int w = wsum[lane];
#pragma unroll
            for (int off = 1; off < 32; off <<= 1) {
                int y = __shfl_up_sync(0xFFFFFFFFu, w, off);
                if (lane >= off) w += y;
            }
            wsum[lane] = w;
        }
        __syncthreads();
        int inc = x + ((wid > 0) ? wsum[wid - 1] : 0);

        if (tid == CSR_THREADS - 1)
            atomicExch(&ready[b], inc + 1);

        if (tid < b) {
            int a;
            do { a = atomicAdd(&ready[tid], 0); } while (a == 0);
            atomicAdd(&s_off, a - 1);
        }
        __syncthreads();
        int off = s_off;

        if (idx < NN) {
            int ip = off + inc;
            g_rowptr[idx + 1] = ip;
            g_cursor[idx]     = ip - v;  // exclusive prefix
        }
        if (idx == 0) g_rowptr[0] = 0;
    }

    grid_barrier(1);

    // ---- phase C: fill (ATOM cursor) ----
    for (int i = gtid; i < NE; i += NT) {
        int d = edge_at(e, (long long)NE + i, is64);
        int s = edge_at(e, i, is64);
        int pos = atomicAdd(&g_cursor[d], 1);
        g_col[pos] = s;
    }
}

// ---------------- GEMM (64x64 tile, known good) ----------------
// out[i,c] = (SCALE ? dis[i] : 1) * sum_k X[i,k]*W[k,c]
// OUTH: fp16 output, row stride NOUT halfs (NOUT multiple of 4).
template <int K, int NOUT, bool SCALE, bool OUTH>
__global__ void __launch_bounds__(128) k_gemm(const float* __restrict__ X,
                                              const float* __restrict__ W,
                                              void* __restrict__ outv) {
    constexpr int BM = 64;
    constexpr int BN = 64;
    constexpr int KC = 32;
    __shared__ float Ws[K][BN];
    __shared__ float Xs[KC][BM + 4];

    int t  = threadIdx.x;
    int m0 = blockIdx.x * BM;
    int rbase = (t >> 4) * 8;
    int cbase = (t & 15) * 4;

    for (int i = t; i < K * BN; i += 128) {
        int k = i / BN, c = i % BN;
        Ws[k][c] = (c < NOUT) ? W[k * NOUT + c] : 0.0f;
    }

    ull acc[4][4];
#pragma unroll
    for (int rp = 0; rp < 4; rp++)
#pragma unroll
        for (int c = 0; c < 4; c++) acc[rp][c] = 0ull;

    __syncthreads();

    for (int kc = 0; kc < K; kc += KC) {
#pragma unroll
        for (int i = 0; i < 4; i++) {
            int v = t + i * 128;
            int r = v >> 3;
            int q = v & 7;
            int row = m0 + r;
            float4 f = make_float4(0.f, 0.f, 0.f, 0.f);
            if (row < NN)
                f = *(const float4*)&X[(size_t)row * K + kc + q * 4];
            Xs[q * 4 + 0][r] = f.x;
            Xs[q * 4 + 1][r] = f.y;
            Xs[q * 4 + 2][r] = f.z;
            Xs[q * 4 + 3][r] = f.w;
        }
        __syncthreads();

#pragma unroll
        for (int kk = 0; kk < KC; kk++) {
            float4 wv = *(const float4*)&Ws[kc + kk][cbase];
            ull wb0 = bcast2(wv.x);
            ull wb1 = bcast2(wv.y);
            ull wb2 = bcast2(wv.z);
            ull wb3 = bcast2(wv.w);
            ulonglong2 xp0 = *(const ulonglong2*)&Xs[kk][rbase];
            ulonglong2 xp1 = *(const ulonglong2*)&Xs[kk][rbase + 4];
            ull xr[4] = {xp0.x, xp0.y, xp1.x, xp1.y};
#pragma unroll
            for (int rp = 0; rp < 4; rp++) {
                fma2(acc[rp][0], xr[rp], wb0);
                fma2(acc[rp][1], xr[rp], wb1);
                fma2(acc[rp][2], xr[rp], wb2);
                fma2(acc[rp][3], xr[rp], wb3);
            }
        }
        __syncthreads();
    }

#pragma unroll
    for (int rp = 0; rp < 4; rp++) {
        int row0 = m0 + rbase + 2 * rp;
        int row1 = row0 + 1;
        float ds0 = 1.f, ds1 = 1.f;
        if (SCALE) {
            ds0 = (row0 < NN) ? g_dis[row0] : 0.f;
            ds1 = (row1 < NN) ? g_dis[row1] : 0.f;
        }
        float v0[4], v1[4];
#pragma unroll
        for (int c = 0; c < 4; c++) unpack2(v0[c], v1[c], acc[rp][c]);

        if (OUTH) {
            __half* out = (__half*)outv;
            if (cbase < NOUT) {
                if (row0 < NN) {
                    __half2 h0 = __floats2half2_rn(v0[0] * ds0, v0[1] * ds0);
                    __half2 h1 = __floats2half2_rn(v0[2] * ds0, v0[3] * ds0);
                    uint2 u; u.x = *(unsigned*)&h0; u.y = *(unsigned*)&h1;
                    *(uint2*)&out[(size_t)row0 * NOUT + cbase] = u;
                }
                if (row1 < NN) {
                    __half2 h0 = __floats2half2_rn(v1[0] * ds1, v1[1] * ds1);
                    __half2 h1 = __floats2half2_rn(v1[2] * ds1, v1[3] * ds1);
                    uint2 u; u.x = *(unsigned*)&h0; u.y = *(unsigned*)&h1;
                    *(uint2*)&out[(size_t)row1 * NOUT + cbase] = u;
                }
            }
        } else {
            float* out = (float*)outv;
#pragma unroll
            for (int c = 0; c < 4; c++) {
                int cc = cbase + c;
                if (cc < NOUT) {
                    if (row0 < NN) out[(size_t)row0 * NOUT + cc] = v0[c] * ds0;
                    if (row1 < NN) out[(size_t)row1 * NOUT + cc] = v1[c] * ds1;
                }
            }
        }
    }
}

// ---------------- fp16 aggregation (F=64): warp per node, fp32 accumulate ----------------
template <bool SRCSCALE>
__global__ void __launch_bounds__(256) k_agg_h(const __half2* __restrict__ H,
                                               const float* __restrict__ bias,
                                               float* __restrict__ out) {
    constexpr int L = FHID / 2;  // 32 half2 per row = full warp
    int warp = (blockIdx.x * blockDim.x + threadIdx.x) >> 5;
    int lane = threadIdx.x & 31;
    if (warp >= NN) return;

    int s = g_rowptr[warp];
    int e = g_rowptr[warp + 1];
    float dn = g_dis[warp];

    float2 self = __half22float2(H[(size_t)warp * L + lane]);
    float sc = SRCSCALE ? dn : 1.f;
    float ax = self.x * sc, ay = self.y * sc;

    int j = s;
    for (; j + 4 <= e; j += 4) {
        int i0 = g_col[j], i1 = g_col[j + 1], i2 = g_col[j + 2], i3 = g_col[j + 3];
        float2 a = __half22float2(H[(size_t)i0 * L + lane]);
        float2 b = __half22float2(H[(size_t)i1 * L + lane]);
        float2 c = __half22float2(H[(size_t)i2 * L + lane]);
        float2 d = __half22float2(H[(size_t)i3 * L + lane]);
        if (SRCSCALE) {
            float d0 = g_dis[i0], d1 = g_dis[i1], d2 = g_dis[i2], d3 = g_dis[i3];
            ax = fmaf(a.x, d0, ax); ay = fmaf(a.y, d0, ay);
            ax = fmaf(b.x, d1, ax); ay = fmaf(b.y, d1, ay);
            ax = fmaf(c.x, d2, ax); ay = fmaf(c.y, d2, ay);
            ax = fmaf(d.x, d3, ax); ay = fmaf(d.y, d3, ay);
        } else {
            ax += (a.x + b.x) + (c.x + d.x);
            ay += (a.y + b.y) + (c.y + d.y);
        }
    }
    for (; j < e; j++) {
        int i0 = g_col[j];
        float2 a = __half22float2(H[(size_t)i0 * L + lane]);
        if (SRCSCALE) {
            float d0 = g_dis[i0];
            ax = fmaf(a.x, d0, ax); ay = fmaf(a.y, d0, ay);
        } else {
            ax += a.x; ay += a.y;
        }
    }

    float2 bv = ((const float2*)bias)[lane];
    float ox = fmaxf(fmaf(ax, dn, bv.x), 0.f);
    float oy = fmaxf(fmaf(ay, dn, bv.y), 0.f);
    float2 r; r.x = ox; r.y = oy;
    ((float2*)out)[(size_t)warp * L + lane] = r;
}

// ---------------- final aggregation + log_softmax (F=40, fp16 messages) ----------------
// Also re-zeros the CSR housekeeping state for the NEXT launch.
__global__ void __launch_bounds__(256) k_agg_final(const __half2* __restrict__ H,
                                                   const float* __restrict__ bias,
                                                   float* __restrict__ out) {
    constexpr int L = FOUT / 2;  // 20 half2 lanes
    int gtid = blockIdx.x * blockDim.x + threadIdx.x;
    int warp = gtid >> 5;
    int lane = threadIdx.x & 31;

    // housekeeping for the next launch (before any early return):
    if (warp < NN && lane == 0) g_zero[warp] = 0;
    if (gtid < 128) g_zero[NN + gtid] = 0;
    if (gtid < 2)   g_barrier[gtid] = 0;

    if (warp >= NN) return;

    int s = g_rowptr[warp];
    int e = g_rowptr[warp + 1];

    float ax = 0.f, ay = 0.f;
    if (lane < L) {
        float2 self = __half22float2(H[(size_t)warp * L + lane]);
        ax = self.x; ay = self.y;
    }
    int j = s;
    for (; j + 4 <= e; j += 4) {
        int i0 = g_col[j], i1 = g_col[j + 1], i2 = g_col[j + 2], i3 = g_col[j + 3];
        if (lane < L) {
            float2 a = __half22float2(H[(size_t)i0 * L + lane]);
            float2 b = __half22float2(H[(size_t)i1 * L + lane]);
            float2 c = __half22float2(H[(size_t)i2 * L + lane]);
            float2 d = __half22float2(H[(size_t)i3 * L + lane]);
            ax += (a.x + b.x) + (c.x + d.x);
            ay += (a.y + b.y) + (c.y + d.y);
        }
    }
    for (; j < e; j++) {
        int i0 = g_col[j];
        if (lane < L) {
            float2 a = __half22float2(H[(size_t)i0 * L + lane]);
            ax += a.x; ay += a.y;
        }
    }

    float vx = -INFINITY, vy = -INFINITY;
    if (lane < L) {
        float dn = g_dis[warp];
        float2 bv = ((const float2*)bias)[lane];
        vx = fmaf(ax, dn, bv.x);
        vy = fmaf(ay, dn, bv.y);
    }

    float m = fmaxf(vx, vy);
#pragma unroll
    for (int off = 16; off > 0; off >>= 1)
        m = fmaxf(m, __shfl_xor_sync(0xFFFFFFFFu, m, off));

    float se = 0.f;
    if (lane < L) se = expf(vx - m) + expf(vy - m);
#pragma unroll
    for (int off = 16; off > 0; off >>= 1)
        se += __shfl_xor_sync(0xFFFFFFFFu, se, off);

    float ls = logf(se);
    if (lane < L) {
        float2 r; r.x = vx - m - ls; r.y = vy - m - ls;
        ((float2*)out)[(size_t)warp * L + lane] = r;
    }
}

// ---------------- launch ----------------
extern "C" void kernel_launch(void* const* d_in, const int* in_sizes, int n_in,
                              void* d_out, int out_size) {
    const float* x  = (const float*)d_in[0];
    const void*  ei = d_in[1];
    const float* W1 = (const float*)d_in[2];
    const float* b1 = (const float*)d_in[3];
    const float* W2 = (const float*)d_in[4];
    const float* b2 = (const float*)d_in[5];
    const float* W3 = (const float*)d_in[6];
    const float* b3 = (const float*)d_in[7];

    void *pHh = nullptr, *pZ = nullptr;
    cudaGetSymbolAddress(&pHh, g_Hh);
    cudaGetSymbolAddress(&pZ, g_Z);
    __half2* Hh = (__half2*)pHh;
    float*   Z  = (float*)pZ;

    const int TB = 256;
    int gGemm = (NN + 63) / 64;
    int gAgg  = (NN * 32 + TB - 1) / TB;

    // Fork: GEMM1 (no CSR dependency; dis-scaling deferred to agg1) overlapped
    // with the one-kernel CSR build.
    cudaEventRecord(g_ss.evFork, 0);
    cudaStreamWaitEvent(g_ss.s1, g_ss.evFork, 0);
    k_gemm<FIN, FHID, false, true><<<gGemm, 128, 0, g_ss.s1>>>(x, W1, pHh);
    cudaEventRecord(g_ss.evJoin, g_ss.s1);

    // Main stream: fused CSR build (hist -> scan -> fill, grid barriers inside;
    // histogram/flags/barriers pre-zeroed by previous launch's agg_final).
    k_csr<<<CSR_BLOCKS, CSR_THREADS>>>(ei);

    // Join, then layer 1 aggregation (applies src-side dis)
    cudaStreamWaitEvent(0, g_ss.evJoin, 0);
    k_agg_h<true><<<gAgg, TB>>>(Hh, b1, Z);

    // Layer 2 (dis folded into GEMM epilogue)
    k_gemm<FHID, FHID, true, true><<<gGemm, 128>>>(Z, W2, pHh);
    k_agg_h<false><<<gAgg, TB>>>(Hh, b2, Z);

    // Layer 3 (fp16 messages)
    k_gemm<FHID, FOUT, true, true><<<gGemm, 128>>>(Z, W3, pHh);
    k_agg_final<<<gAgg, TB>>>(Hh, b3, (float*)d_out);
}

// round 15
// speedup vs baseline: 1.1353x; 1.1353x over previous
#include <cuda_runtime.h>
#include <cuda_fp16.h>
#include <math.h>

#define NN 100000
#define NE 1200000
#define FIN 128
#define FHID 64
#define FOUT 40

typedef unsigned long long ull;

// ---------------- scratch (device globals) ----------------
// g_zero: [0,NN) = degree histogram, [NN, NN+128) = scan ready-flags. One memset.
__device__ int    g_zero[NN + 128];
__device__ int    g_rowptr[NN + 1];
__device__ int    g_cursor[NN];
__device__ int    g_col[NE];
__device__ float  g_dis[NN];
__device__ __half g_Hh[(size_t)NN * FHID];  // fp16 message buffer (layers 1-3)
__device__ float  g_Z[(size_t)NN * FHID];   // aggregated fp32 buffer

constexpr int SCAN_B = 1024;
constexpr int NBLK   = (NN + SCAN_B - 1) / SCAN_B;  // 98

// ---------------- side stream for capture fork-join (created pre-main) ----------------
struct SideStream {
    cudaStream_t s1;
    cudaEvent_t evFork, evJoin;
    SideStream() {
        cudaStreamCreateWithFlags(&s1, cudaStreamNonBlocking);
        cudaEventCreateWithFlags(&evFork, cudaEventDisableTiming);
        cudaEventCreateWithFlags(&evJoin, cudaEventDisableTiming);
    }
};
static SideStream g_ss;

// ---------------- packed f32x2 helpers (Blackwell FFMA2) ----------------
__device__ __forceinline__ ull bcast2(float f) {
    ull r;
    asm("mov.b64 %0, {%1, %1};" : "=l"(r) : "f"(f));
    return r;
}
__device__ __forceinline__ void fma2(ull& d, ull a, ull b) {
    asm("fma.rn.f32x2 %0, %1, %2, %0;" : "+l"(d) : "l"(a), "l"(b));
}
__device__ __forceinline__ void unpack2(float& lo, float& hi, ull v) {
    asm("mov.b64 {%0, %1}, %2;" : "=f"(lo), "=f"(hi) : "l"(v));
}

// ---------------- per-block edge dtype detection ----------------
__device__ __forceinline__ int detect_is64(const int* e) {
    int t = threadIdx.x;
    int pred = 1;
    if (t < 128) pred = (e[2 * t + 1] == 0);
    return __syncthreads_and(pred);
}

__device__ __forceinline__ int edge_at(const void* e, long long idx, int is64) {
    if (is64) return (int)((const long long*)e)[idx];
    return ((const int*)e)[idx];
}

// ---------------- degree histogram (RED path: atomic result unused) ----------------
__global__ void k_hist(const void* __restrict__ e) {
    int is64 = detect_is64((const int*)e);
    int i = blockIdx.x * blockDim.x + threadIdx.x;
    if (i < NE) {
        int d = edge_at(e, (long long)NE + i, is64);
        atomicAdd(&g_zero[d], 1);
    }
}

// ---------------- single-pass scan: deg -> rowptr, cursor, dis ----------------
__global__ void __launch_bounds__(SCAN_B) k_scan_fused() {
    __shared__ int wsum[32];
    __shared__ int s_off;
    int b    = blockIdx.x;
    int tid  = threadIdx.x;
    int lane = tid & 31;
    int wid  = tid >> 5;
    int idx  = b * SCAN_B + tid;
    int* ready = &g_zero[NN];

    int v = (idx < NN) ? g_zero[idx] : 0;
    if (idx < NN) g_dis[idx] = rsqrtf((float)(v + 1));
    if (tid == 0) s_off = 0;

    int x = v;
#pragma unroll
    for (int off = 1; off < 32; off <<= 1) {
        int y = __shfl_up_sync(0xFFFFFFFFu, x, off);
        if (lane >= off) x += y;
    }
    if (lane == 31) wsum[wid] = x;
    __syncthreads();
    if (wid == 0) {
        int w = wsum[lane];
#pragma unroll
        for (int off = 1; off < 32; off <<= 1) {
            int y = __shfl_up_sync(0xFFFFFFFFu, w, off);
            if (lane >= off) w += y;
        }
        wsum[lane] = w;
    }
    __syncthreads();
    int inc = x + ((wid > 0) ? wsum[wid - 1] : 0);

    if (tid == SCAN_B - 1)
        atomicExch(&ready[b], inc + 1);

    if (tid < b) {
        int a;
        do { a = atomicAdd(&ready[tid], 0); } while (a == 0);
        atomicAdd(&s_off, a - 1);
    }
    __syncthreads();
    int off = s_off;

    if (idx < NN) {
        int ip = off + inc;
        g_rowptr[idx + 1] = ip;
        g_cursor[idx]     = ip - v;  // exclusive prefix
    }
    if (idx == 0) g_rowptr[0] = 0;
}

// ---------------- CSR fill (ATOM cursor) ----------------
__global__ void k_fill(const void* __restrict__ e) {
    int is64 = detect_is64((const int*)e);
    int i = blockIdx.x * blockDim.x + threadIdx.x;
    if (i < NE) {
        int d = edge_at(e, (long long)NE + i, is64);
        int s = edge_at(e, i, is64);
        int pos = atomicAdd(&g_cursor[d], 1);
        g_col[pos] = s;
    }
}

// ---------------- GEMM (64x64 tile, fp16 W tile for occupancy) ----------------
// out[i,c] = (SCALE ? dis[i] : 1) * sum_k X[i,k]*W[k,c]
// Ws in smem is fp16 (halves Ws footprint: 13 blocks/SM vs 9).
// OUTH: fp16 output, row stride NOUT halfs (NOUT multiple of 4).
template <int K, int NOUT, bool SCALE, bool OUTH>
__global__ void __launch_bounds__(128) k_gemm(const float* __restrict__ X,
                                              const float* __restrict__ W,
                                              void* __restrict__ outv) {
    constexpr int BM = 64;
    constexpr int BN = 64;
    constexpr int KC = 32;
    __shared__ __half Ws[K][BN];          // fp16 weight tile
    __shared__ float  Xs[KC][BM + 4];

    int t  = threadIdx.x;
    int m0 = blockIdx.x * BM;
    int rbase = (t >> 4) * 8;
    int cbase = (t & 15) * 4;

    for (int i = t; i < K * BN; i += 128) {
        int k = i / BN, c = i % BN;
        Ws[k][c] = __float2half((c < NOUT) ? W[k * NOUT + c] : 0.0f);
    }

    ull acc[4][4];
#pragma unroll
    for (int rp = 0; rp < 4; rp++)
#pragma unroll
        for (int c = 0; c < 4; c++) acc[rp][c] = 0ull;

    __syncthreads();

    for (int kc = 0; kc < K; kc += KC) {
#pragma unroll
        for (int i = 0; i < 4; i++) {
            int v = t + i * 128;
            int r = v >> 3;
            int q = v & 7;
            int row = m0 + r;
            float4 f = make_float4(0.f, 0.f, 0.f, 0.f);
            if (row < NN)
                f = *(const float4*)&X[(size_t)row * K + kc + q * 4];
            Xs[q * 4 + 0][r] = f.x;
            Xs[q * 4 + 1][r] = f.y;
            Xs[q * 4 + 2][r] = f.z;
            Xs[q * 4 + 3][r] = f.w;
        }
        __syncthreads();

#pragma unroll
        for (int kk = 0; kk < KC; kk++) {
            // 4 fp16 weights = one 8-byte LDS, two converts
            __half2 wh[2];
            *(uint2*)wh = *(const uint2*)&Ws[kc + kk][cbase];
            float2 w01 = __half22float2(wh[0]);
            float2 w23 = __half22float2(wh[1]);
            ull wb0 = bcast2(w01.x);
            ull wb1 = bcast2(w01.y);
            ull wb2 = bcast2(w23.x);
            ull wb3 = bcast2(w23.y);
            ulonglong2 xp0 = *(const ulonglong2*)&Xs[kk][rbase];
            ulonglong2 xp1 = *(const ulonglong2*)&Xs[kk][rbase + 4];
            ull xr[4] = {xp0.x, xp0.y, xp1.x, xp1.y};
#pragma unroll
            for (int rp = 0; rp < 4; rp++) {
                fma2(acc[rp][0], xr[rp], wb0);
                fma2(acc[rp][1], xr[rp], wb1);
                fma2(acc[rp][2], xr[rp], wb2);
                fma2(acc[rp][3], xr[rp], wb3);
            }
        }
        __syncthreads();
    }

#pragma unroll
    for (int rp = 0; rp < 4; rp++) {
        int row0 = m0 + rbase + 2 * rp;
        int row1 = row0 + 1;
        float ds0 = 1.f, ds1 = 1.f;
        if (SCALE) {
            ds0 = (row0 < NN) ? g_dis[row0] : 0.f;
            ds1 = (row1 < NN) ? g_dis[row1] : 0.f;
        }
        float v0[4], v1[4];
#pragma unroll
        for (int c = 0; c < 4; c++) unpack2(v0[c], v1[c], acc[rp][c]);

        if (OUTH) {
            __half* out = (__half*)outv;
            if (cbase < NOUT) {
                if (row0 < NN) {
                    __half2 h0 = __floats2half2_rn(v0[0] * ds0, v0[1] * ds0);
                    __half2 h1 = __floats2half2_rn(v0[2] * ds0, v0[3] * ds0);
                    uint2 u; u.x = *(unsigned*)&h0; u.y = *(unsigned*)&h1;
                    *(uint2*)&out[(size_t)row0 * NOUT + cbase] = u;
                }
                if (row1 < NN) {
                    __half2 h0 = __floats2half2_rn(v1[0] * ds1, v1[1] * ds1);
                    __half2 h1 = __floats2half2_rn(v1[2] * ds1, v1[3] * ds1);
                    uint2 u; u.x = *(unsigned*)&h0; u.y = *(unsigned*)&h1;
                    *(uint2*)&out[(size_t)row1 * NOUT + cbase] = u;
                }
            }
        } else {
            float* out = (float*)outv;
#pragma unroll
            for (int c = 0; c < 4; c++) {
                int cc = cbase + c;
                if (cc < NOUT) {
                    if (row0 < NN) out[(size_t)row0 * NOUT + cc] = v0[c] * ds0;
                    if (row1 < NN) out[(size_t)row1 * NOUT + cc] = v1[c] * ds1;
                }
            }
        }
    }
}

// ---------------- fp16 aggregation (F=64): warp per node, fp32 accumulate ----------------
template <bool SRCSCALE>
__global__ void __launch_bounds__(256) k_agg_h(const __half2* __restrict__ H,
                                               const float* __restrict__ bias,
                                               float* __restrict__ out) {
    constexpr int L = FHID / 2;  // 32 half2 per row = full warp
    int warp = (blockIdx.x * blockDim.x + threadIdx.x) >> 5;
    int lane = threadIdx.x & 31;
    if (warp >= NN) return;

    int s = g_rowptr[warp];
    int e = g_rowptr[warp + 1];
    float dn = g_dis[warp];

    float2 self = __half22float2(H[(size_t)warp * L + lane]);
    float sc = SRCSCALE ? dn : 1.f;
    float ax = self.x * sc, ay = self.y * sc;

    int j = s;
    for (; j + 4 <= e; j += 4) {
        int i0 = g_col[j], i1 = g_col[j + 1], i2 = g_col[j + 2], i3 = g_col[j + 3];
        float2 a = __half22float2(H[(size_t)i0 * L + lane]);
        float2 b = __half22float2(H[(size_t)i1 * L + lane]);
        float2 c = __half22float2(H[(size_t)i2 * L + lane]);
        float2 d = __half22float2(H[(size_t)i3 * L + lane]);
        if (SRCSCALE) {
            float d0 = g_dis[i0], d1 = g_dis[i1], d2 = g_dis[i2], d3 = g_dis[i3];
            ax = fmaf(a.x, d0, ax); ay = fmaf(a.y, d0, ay);
            ax = fmaf(b.x, d1, ax); ay = fmaf(b.y, d1, ay);
            ax = fmaf(c.x, d2, ax); ay = fmaf(c.y, d2, ay);
            ax = fmaf(d.x, d3, ax); ay = fmaf(d.y, d3, ay);
        } else {
            ax += (a.x + b.x) + (c.x + d.x);
            ay += (a.y + b.y) + (c.y + d.y);
        }
    }
    for (; j < e; j++) {
        int i0 = g_col[j];
        float2 a = __half22float2(H[(size_t)i0 * L + lane]);
        if (SRCSCALE) {
            float d0 = g_dis[i0];
            ax = fmaf(a.x, d0, ax); ay = fmaf(a.y, d0, ay);
        } else {
            ax += a.x; ay += a.y;
        }
    }

    float2 bv = ((const float2*)bias)[lane];
    float ox = fmaxf(fmaf(ax, dn, bv.x), 0.f);
    float oy = fmaxf(fmaf(ay, dn, bv.y), 0.f);
    float2 r; r.x = ox; r.y = oy;
    ((float2*)out)[(size_t)warp * L + lane] = r;
}

// ---------------- final aggregation + bias + log_softmax (F=40, fp16 messages) ----------------
__global__ void __launch_bounds__(256) k_agg_final(const __half2* __restrict__ H,
                                                   const float* __restrict__ bias,
                                                   float* __restrict__ out) {
    constexpr int L = FOUT / 2;  // 20 half2 lanes
    int warp = (blockIdx.x * blockDim.x + threadIdx.x) >> 5;
    int lane = threadIdx.x & 31;
    if (warp >= NN) return;

    int s = g_rowptr[warp];
    int e = g_rowptr[warp + 1];

    float ax = 0.f, ay = 0.f;
    if (lane < L) {
        float2 self = __half22float2(H[(size_t)warp * L + lane]);
        ax = self.x; ay = self.y;
    }
    int j = s;
    for (; j + 4 <= e; j += 4) {
        int i0 = g_col[j], i1 = g_col[j + 1], i2 = g_col[j + 2], i3 = g_col[j + 3];
        if (lane < L) {
            float2 a = __half22float2(H[(size_t)i0 * L + lane]);
            float2 b = __half22float2(H[(size_t)i1 * L + lane]);
            float2 c = __half22float2(H[(size_t)i2 * L + lane]);
            float2 d = __half22float2(H[(size_t)i3 * L + lane]);
            ax += (a.x + b.x) + (c.x + d.x);
            ay += (a.y + b.y) + (c.y + d.y);
        }
    }
    for (; j < e; j++) {
        int i0 = g_col[j];
        if (lane < L) {
            float2 a = __half22float2(H[(size_t)i0 * L + lane]);
            ax += a.x; ay += a.y;
        }
    }

    float vx = -INFINITY, vy = -INFINITY;
    if (lane < L) {
        float dn = g_dis[warp];
        float2 bv = ((const float2*)bias)[lane];
        vx = fmaf(ax, dn, bv.x);
        vy = fmaf(ay, dn, bv.y);
    }

    float m = fmaxf(vx, vy);
#pragma unroll
    for (int off = 16; off > 0; off >>= 1)
        m = fmaxf(m, __shfl_xor_sync(0xFFFFFFFFu, m, off));

    float se = 0.f;
    if (lane < L) se = expf(vx - m) + expf(vy - m);
#pragma unroll
    for (int off = 16; off > 0; off >>= 1)
        se += __shfl_xor_sync(0xFFFFFFFFu, se, off);

    float ls = logf(se);
    if (lane < L) {
        float2 r; r.x = vx - m - ls; r.y = vy - m - ls;
        ((float2*)out)[(size_t)warp * L + lane] = r;
    }
}

// ---------------- launch ----------------
extern "C" void kernel_launch(void* const* d_in, const int* in_sizes, int n_in,
                              void* d_out, int out_size) {
    const float* x  = (const float*)d_in[0];
    const void*  ei = d_in[1];
    const float* W1 = (const float*)d_in[2];
    const float* b1 = (const float*)d_in[3];
    const float* W2 = (const float*)d_in[4];
    const float* b2 = (const float*)d_in[5];
    const float* W3 = (const float*)d_in[6];
    const float* b3 = (const float*)d_in[7];

    void *pHh = nullptr, *pZ = nullptr, *pZero = nullptr;
    cudaGetSymbolAddress(&pHh, g_Hh);
    cudaGetSymbolAddress(&pZ, g_Z);
    cudaGetSymbolAddress(&pZero, g_zero);
    __half2* Hh = (__half2*)pHh;
    float*   Z  = (float*)pZ;

    const int TB = 256;
    int gE = (NE + TB - 1) / TB;
    int gGemm = (NN + 63) / 64;
    int gAgg  = (NN * 32 + TB - 1) / TB;

    // Fork: GEMM1 (no CSR dependency; dis-scaling deferred to agg1) overlapped
    // with the CSR build.
    cudaEventRecord(g_ss.evFork, 0);
    cudaStreamWaitEvent(g_ss.s1, g_ss.evFork, 0);
    k_gemm<FIN, FHID, false, true><<<gGemm, 128, 0, g_ss.s1>>>(x, W1, pHh);
    cudaEventRecord(g_ss.evJoin, g_ss.s1);

    // Main stream: CSR build (hist = RED path, fill = ATOM cursor)
    cudaMemsetAsync(pZero, 0, (NN + 128) * sizeof(int));
    k_hist<<<gE, TB>>>(ei);
    k_scan_fused<<<NBLK, SCAN_B>>>();
    k_fill<<<gE, TB>>>(ei);

    // Join, then layer 1 aggregation (applies src-side dis)
    cudaStreamWaitEvent(0, g_ss.evJoin, 0);
    k_agg_h<true><<<gAgg, TB>>>(Hh, b1, Z);

    // Layer 2 (dis folded into GEMM epilogue)
    k_gemm<FHID, FHID, true, true><<<gGemm, 128>>>(Z, W2, pHh);
    k_agg_h<false><<<gAgg, TB>>>(Hh, b2, Z);

    // Layer 3 (fp16 messages)
    k_gemm<FHID, FOUT, true, true><<<gGemm, 128>>>(Z, W3, pHh);
    k_agg_final<<<gAgg, TB>>>(Hh, b3, (float*)d_out);
}

// round 17
// speedup vs baseline: 1.2984x; 1.1436x over previous
#include <cuda_runtime.h>
#include <cuda_fp16.h>
#include <mma.h>
#include <math.h>

using namespace nvcuda;

#define NN 100000
#define NE 1200000
#define FIN 128
#define FHID 64
#define FOUT 40

typedef unsigned long long ull;

// ---------------- scratch (device globals) ----------------
// g_zero: [0,NN) = degree histogram, [NN, NN+128) = scan ready-flags. One memset.
__device__ int    g_zero[NN + 128];
__device__ int    g_rowptr[NN + 1];
__device__ int    g_cursor[NN];
__device__ int    g_col[NE];
__device__ float  g_dis[NN];
__device__ __half g_Hh[(size_t)NN * FHID];  // fp16 message buffer (all layers)
__device__ __half g_Zh[(size_t)NN * FHID];  // fp16 aggregated buffer (GEMM input)

constexpr int SCAN_B = 1024;
constexpr int NBLK   = (NN + SCAN_B - 1) / SCAN_B;  // 98

// ---------------- side stream for capture fork-join (created pre-main) ----------------
struct SideStream {
    cudaStream_t s1;
    cudaEvent_t evFork, evJoin;
    SideStream() {
        cudaStreamCreateWithFlags(&s1, cudaStreamNonBlocking);
        cudaEventCreateWithFlags(&evFork, cudaEventDisableTiming);
        cudaEventCreateWithFlags(&evJoin, cudaEventDisableTiming);
    }
};
static SideStream g_ss;

// ---------------- per-block edge dtype detection ----------------
__device__ __forceinline__ int detect_is64(const int* e) {
    int t = threadIdx.x;
    int pred = 1;
    if (t < 128) pred = (e[2 * t + 1] == 0);
    return __syncthreads_and(pred);
}

__device__ __forceinline__ int edge_at(const void* e, long long idx, int is64) {
    if (is64) return (int)((const long long*)e)[idx];
    return ((const int*)e)[idx];
}

// ---------------- degree histogram (RED path: atomic result unused) ----------------
__global__ void k_hist(const void* __restrict__ e) {
    int is64 = detect_is64((const int*)e);
    int i = blockIdx.x * blockDim.x + threadIdx.x;
    if (i < NE) {
        int d = edge_at(e, (long long)NE + i, is64);
        atomicAdd(&g_zero[d], 1);
    }
}

// ---------------- single-pass scan: deg -> rowptr, cursor, dis ----------------
__global__ void __launch_bounds__(SCAN_B) k_scan_fused() {
    __shared__ int wsum[32];
    __shared__ int s_off;
    int b    = blockIdx.x;
    int tid  = threadIdx.x;
    int lane = tid & 31;
    int wid  = tid >> 5;
    int idx  = b * SCAN_B + tid;
    int* ready = &g_zero[NN];

    int v = (idx < NN) ? g_zero[idx] : 0;
    if (idx < NN) g_dis[idx] = rsqrtf((float)(v + 1));
    if (tid == 0) s_off = 0;

    int x = v;
#pragma unroll
    for (int off = 1; off < 32; off <<= 1) {
        int y = __shfl_up_sync(0xFFFFFFFFu, x, off);
        if (lane >= off) x += y;
    }
    if (lane == 31) wsum[wid] = x;
    __syncthreads();
    if (wid == 0) {
        int w = wsum[lane];
#pragma unroll
        for (int off = 1; off < 32; off <<= 1) {
            int y = __shfl_up_sync(0xFFFFFFFFu, w, off);
            if (lane >= off) w += y;
        }
        wsum[lane] = w;
    }
    __syncthreads();
    int inc = x + ((wid > 0) ? wsum[wid - 1] : 0);

    if (tid == SCAN_B - 1)
        atomicExch(&ready[b], inc + 1);

    if (tid < b) {
        int a;
        do { a = atomicAdd(&ready[tid], 0); } while (a == 0);
        atomicAdd(&s_off, a - 1);
    }
    __syncthreads();
    int off = s_off;

    if (idx < NN) {
        int ip = off + inc;
        g_rowptr[idx + 1] = ip;
        g_cursor[idx]     = ip - v;  // exclusive prefix
    }
    if (idx == 0) g_rowptr[0] = 0;
}

// ---------------- CSR fill (ATOM cursor) ----------------
__global__ void k_fill(const void* __restrict__ e) {
    int is64 = detect_is64((const int*)e);
    int i = blockIdx.x * blockDim.x + threadIdx.x;
    if (i < NE) {
        int d = edge_at(e, (long long)NE + i, is64);
        int s = edge_at(e, i, is64);
        int pos = atomicAdd(&g_cursor[d], 1);
        g_col[pos] = s;
    }
}

// ---------------- wmma GEMM (tensor cores; fp16 in, fp32 accum, fp16 out) ----------------
// out[i,c] = (SCALE ? dis[i] : 1) * sum_k in[i,k]*W[k,c]
// 64-row tile, 4 warps, each warp 16 rows x 64 cols (4 n-fragments).
template <int K, int NOUT, bool SCALE, bool INHALF>
__global__ void __launch_bounds__(128) k_gemm_w(const void* __restrict__ inv,
                                                const float* __restrict__ W,
                                                __half* __restrict__ out) {
    constexpr int LDA = K + 8;    // halfs; multiple of 8
    constexpr int LDW = 72;       // halfs
    constexpr int LDC = 24;       // floats
    __shared__ __half As[64 * LDA];
    __shared__ __half Ws[K * LDW];
    __shared__ float  Cs[4 * 16 * LDC];

    int t    = threadIdx.x;
    int w    = t >> 5;
    int lane = t & 31;
    int m0   = blockIdx.x * 64;

    // ---- load A tile (convert to fp16 if needed) ----
    if (INHALF) {
        const __half* in = (const __half*)inv;
        constexpr int QW = K / 8;           // uint4 = 8 halfs
        for (int i = t; i < 64 * QW; i += 128) {
            int r = i / QW, q = i % QW;
            int row = m0 + r;
            uint4 v = make_uint4(0u, 0u, 0u, 0u);
            if (row < NN) v = *(const uint4*)&in[(size_t)row * K + q * 8];
            *(uint4*)&As[r * LDA + q * 8] = v;
        }
    } else {
        const float* in = (const float*)inv;
        constexpr int QF = K / 4;           // float4 = 4 floats -> 4 halfs
        for (int i = t; i < 64 * QF; i += 128) {
            int r = i / QF, q = i % QF;
            int row = m0 + r;
            float4 f = make_float4(0.f, 0.f, 0.f, 0.f);
            if (row < NN) f = *(const float4*)&in[(size_t)row * K + q * 4];
            __half2 h0 = __floats2half2_rn(f.x, f.y);
            __half2 h1 = __floats2half2_rn(f.z, f.w);
            uint2 u; u.x = *(unsigned*)&h0; u.y = *(unsigned*)&h1;
            *(uint2*)&As[r * LDA + q * 4] = u;
        }
    }

    // ---- load W [K x NOUT] fp32 -> fp16 smem, zero-pad to 64 cols ----
    for (int i = t; i < K * 64; i += 128) {
        int k = i >> 6, c = i & 63;
        Ws[k * LDW + c] = __float2half((c < NOUT) ? W[k * NOUT + c] : 0.f);
    }
    __syncthreads();

    // ---- mma ----
    wmma::fragment<wmma::accumulator, 16, 16, 16, float> acc[4];
#pragma unroll
    for (int n = 0; n < 4; n++) wmma::fill_fragment(acc[n], 0.f);

#pragma unroll
    for (int k = 0; k < K; k += 16) {
        wmma::fragment<wmma::matrix_a, 16, 16, 16, __half, wmma::row_major> af;
        wmma::load_matrix_sync(af, &As[(w * 16) * LDA + k], LDA);
#pragma unroll
        for (int n = 0; n < 4; n++) {
            wmma::fragment<wmma::matrix_b, 16, 16, 16, __half, wmma::row_major> bf;
            wmma::load_matrix_sync(bf, &Ws[k * LDW + n * 16], LDW);
            wmma::mma_sync(acc[n], af, bf, acc[n]);
        }
    }

    // ---- epilogue: per-warp scratch, dis scale, fp16 store ----
    float* cs = &Cs[w * 16 * LDC];
#pragma unroll
    for (int n = 0; n < 4; n++) {
        int c0 = n * 16;
        if (c0 >= NOUT) break;
        wmma::store_matrix_sync(cs, acc[n], LDC, wmma::mem_row_major);
        __syncwarp();
        for (int idx = lane; idx < 16 * 16; idx += 32) {
            int r = idx >> 4, c = idx & 15;
            int row = m0 + w * 16 + r;
            int col = c0 + c;
            if (row < NN && col < NOUT) {
                float ds = SCALE ? g_dis[row] : 1.f;
                out[(size_t)row * NOUT + col] = __float2half(cs[r * LDC + c] * ds);
            }
        }
        __syncwarp();
    }
}

// ---------------- fp16 aggregation (F=64): warp per node, fp32 accumulate, fp16 out ----------------
// SRCSCALE=false: H pre-scaled by dis; out = relu(dis[d]*(Σ H[s] + H[d]) + b)
// SRCSCALE=true : H unscaled;         out = relu(dis[d]*(Σ dis[s]H[s] + dis[d]H[d]) + b)
template <bool SRCSCALE>
__global__ void __launch_bounds__(256) k_agg_h(const __half2* __restrict__ H,
                                               const float* __restrict__ bias,
                                               __half2* __restrict__ out) {
    constexpr int L = FHID / 2;  // 32 half2 per row = full warp
    int warp = (blockIdx.x * blockDim.x + threadIdx.x) >> 5;
    int lane = threadIdx.x & 31;
    if (warp >= NN) return;

    int s = g_rowptr[warp];
    int e = g_rowptr[warp + 1];
    float dn = g_dis[warp];

    float2 self = __half22float2(H[(size_t)warp * L + lane]);
    float sc = SRCSCALE ? dn : 1.f;
    float ax = self.x * sc, ay = self.y * sc;

    int j = s;
    for (; j + 4 <= e; j += 4) {
        int i0 = g_col[j], i1 = g_col[j + 1], i2 = g_col[j + 2], i3 = g_col[j + 3];
        float2 a = __half22float2(H[(size_t)i0 * L + lane]);
        float2 b = __half22float2(H[(size_t)i1 * L + lane]);
        float2 c = __half22float2(H[(size_t)i2 * L + lane]);
        float2 d = __half22float2(H[(size_t)i3 * L + lane]);
        if (SRCSCALE) {
            float d0 = g_dis[i0], d1 = g_dis[i1], d2 = g_dis[i2], d3 = g_dis[i3];
            ax = fmaf(a.x, d0, ax); ay = fmaf(a.y, d0, ay);
            ax = fmaf(b.x, d1, ax); ay = fmaf(b.y, d1, ay);
            ax = fmaf(c.x, d2, ax); ay = fmaf(c.y, d2, ay);
            ax = fmaf(d.x, d3, ax); ay = fmaf(d.y, d3, ay);
        } else {
            ax += (a.x + b.x) + (c.x + d.x);
            ay += (a.y + b.y) + (c.y + d.y);
        }
    }
    for (; j < e; j++) {
        int i0 = g_col[j];
        float2 a = __half22float2(H[(size_t)i0 * L + lane]);
        if (SRCSCALE) {
            float d0 = g_dis[i0];
            ax = fmaf(a.x, d0, ax); ay = fmaf(a.y, d0, ay);
        } else {
            ax += a.x; ay += a.y;
        }
    }

    float2 bv = ((const float2*)bias)[lane];
    float ox = fmaxf(fmaf(ax, dn, bv.x), 0.f);
    float oy = fmaxf(fmaf(ay, dn, bv.y), 0.f);
    out[(size_t)warp * L + lane] = __floats2half2_rn(ox, oy);
}

// ---------------- final aggregation + bias + log_softmax (F=40, fp16 messages) ----------------
__global__ void __launch_bounds__(256) k_agg_final(const __half2* __restrict__ H,
                                                   const float* __restrict__ bias,
                                                   float* __restrict__ out) {
    constexpr int L = FOUT / 2;  // 20 half2 lanes
    int warp = (blockIdx.x * blockDim.x + threadIdx.x) >> 5;
    int lane = threadIdx.x & 31;
    if (warp >= NN) return;

    int s = g_rowptr[warp];
    int e = g_rowptr[warp + 1];

    float ax = 0.f, ay = 0.f;
    if (lane < L) {
        float2 self = __half22float2(H[(size_t)warp * L + lane]);
        ax = self.x; ay = self.y;
    }
    int j = s;
    for (; j + 4 <= e; j += 4) {
        int i0 = g_col[j], i1 = g_col[j + 1], i2 = g_col[j + 2], i3 = g_col[j + 3];
        if (lane < L) {
            float2 a = __half22float2(H[(size_t)i0 * L + lane]);
            float2 b = __half22float2(H[(size_t)i1 * L + lane]);
            float2 c = __half22float2(H[(size_t)i2 * L + lane]);
            float2 d = __half22float2(H[(size_t)i3 * L + lane]);
            ax += (a.x + b.x) + (c.x + d.x);
            ay += (a.y + b.y) + (c.y + d.y);
        }
    }
    for (; j < e; j++) {
        int i0 = g_col[j];
        if (lane < L) {
            float2 a = __half22float2(H[(size_t)i0 * L + lane]);
            ax += a.x; ay += a.y;
        }
    }

    float vx = -INFINITY, vy = -INFINITY;
    if (lane < L) {
        float dn = g_dis[warp];
        float2 bv = ((const float2*)bias)[lane];
        vx = fmaf(ax, dn, bv.x);
        vy = fmaf(ay, dn, bv.y);
    }

    float m = fmaxf(vx, vy);
#pragma unroll
    for (int off = 16; off > 0; off >>= 1)
        m = fmaxf(m, __shfl_xor_sync(0xFFFFFFFFu, m, off));

    float se = 0.f;
    if (lane < L) se = expf(vx - m) + expf(vy - m);
#pragma unroll
    for (int off = 16; off > 0; off >>= 1)
        se += __shfl_xor_sync(0xFFFFFFFFu, se, off);

    float ls = logf(se);
    if (lane < L) {
        float2 r; r.x = vx - m - ls; r.y = vy - m - ls;
        ((float2*)out)[(size_t)warp * L + lane] = r;
    }
}

// ---------------- launch ----------------
extern "C" void kernel_launch(void* const* d_in, const int* in_sizes, int n_in,
                              void* d_out, int out_size) {
    const float* x  = (const float*)d_in[0];
    const void*  ei = d_in[1];
    const float* W1 = (const float*)d_in[2];
    const float* b1 = (const float*)d_in[3];
    const float* W2 = (const float*)d_in[4];
    const float* b2 = (const float*)d_in[5];
    const float* W3 = (const float*)d_in[6];
    const float* b3 = (const float*)d_in[7];

    void *pHh = nullptr, *pZh = nullptr, *pZero = nullptr;
    cudaGetSymbolAddress(&pHh, g_Hh);
    cudaGetSymbolAddress(&pZh, g_Zh);
    cudaGetSymbolAddress(&pZero, g_zero);
    __half2* Hh = (__half2*)pHh;

    const int TB = 256;
    int gE = (NE + TB - 1) / TB;
    int gGemm = (NN + 63) / 64;
    int gAgg  = (NN * 32 + TB - 1) / TB;

    // Fork: GEMM1 (no CSR dependency; dis-scaling deferred to agg1) overlapped
    // with the CSR build.
    cudaEventRecord(g_ss.evFork, 0);
    cudaStreamWaitEvent(g_ss.s1, g_ss.evFork, 0);
    k_gemm_w<FIN, FHID, false, false><<<gGemm, 128, 0, g_ss.s1>>>(x, W1, (__half*)pHh);
    cudaEventRecord(g_ss.evJoin, g_ss.s1);

    // Main stream: CSR build (hist = RED path, fill = ATOM cursor)
    cudaMemsetAsync(pZero, 0, (NN + 128) * sizeof(int));
    k_hist<<<gE, TB>>>(ei);
    k_scan_fused<<<NBLK, SCAN_B>>>();
    k_fill<<<gE, TB>>>(ei);

    // Join, then layer 1 aggregation (applies src-side dis), fp16 Z out
    cudaStreamWaitEvent(0, g_ss.evJoin, 0);
    k_agg_h<true><<<gAgg, TB>>>(Hh, b1, (__half2*)pZh);

    // Layer 2 (dis folded into GEMM epilogue)
    k_gemm_w<FHID, FHID, true, true><<<gGemm, 128>>>(pZh, W2, (__half*)pHh);
    k_agg_h<false><<<gAgg, TB>>>(Hh, b2, (__half2*)pZh);

    // Layer 3 (fp16 messages)
    k_gemm_w<FHID, FOUT, true, true><<<gGemm, 128>>>(pZh, W3, (__half*)pHh);
    k_agg_final<<<gAgg, TB>>>(Hh, b3, (float*)d_out);
}